// round 4
// baseline (speedup 1.0000x reference)
#include <cuda_runtime.h>
#include <float.h>

// ---------------- scratch (no allocs allowed) ----------------
__device__ float g_dist0[10][65536];   // 253*253 padded to 256*256
__device__ float g_dist1[5][16384];    // 127*127 padded
__device__ float g_contrib[16];

// ---------------- scale 0: ps=3, C=64, 256x256, 10 targets ----------------
#define CB 16   // channel chunk

__global__ __launch_bounds__(256) void scale0_kernel(
    const float* __restrict__ src, const float* __restrict__ tgt,
    const int* __restrict__ pos)
{
    __shared__ __align__(16) float win[CB][10][34];  // (8+2) x (32+2) window
    __shared__ __align__(16) float tp[CB][12];       // 9 used, padded for float4

    const int tid  = threadIdx.x;
    const int tile = blockIdx.x;          // 0..255 : 8 tiles in x, 32 in y
    const int t    = blockIdx.y;          // target 0..9
    const int w0   = (tile & 7) * 32;
    const int h0   = (tile >> 3) * 8;
    const int th   = pos[2 * t];
    const int tw   = pos[2 * t + 1];
    const int hl   = tid >> 5;            // 0..7
    const int wl   = tid & 31;            // 0..31

    float acc0 = 0.f, acc1 = 0.f;

    for (int cb = 0; cb < 64; cb += CB) {
        // cooperative load of src window (clamped at image edge; clamped rows
        // feed only invalid patches)
        for (int l = tid; l < CB * 10 * 34; l += 256) {
            int c = l / 340;
            int r = (l - c * 340) / 34;
            int x = l - c * 340 - r * 34;
            int gy = min(h0 + r, 255);
            int gx = min(w0 + x, 255);
            win[c][r][x] = src[(cb + c) * 65536 + gy * 256 + gx];
        }
        // target patch chunk
        if (tid < CB * 9) {
            int c = tid / 9;
            int k = tid - c * 9;
            int i = k / 3, j = k - i * 3;
            tp[c][k] = tgt[(cb + c) * 65536 + (th + i) * 256 + (tw + j)];
        }
        __syncthreads();

        #pragma unroll
        for (int c = 0; c < CB; ++c) {
            float4 ta = *(const float4*)&tp[c][0];
            float4 tb = *(const float4*)&tp[c][4];
            float  t8 = tp[c][8];
            const float* p0 = &win[c][hl][wl];
            const float* p1 = &win[c][hl + 1][wl];
            const float* p2 = &win[c][hl + 2][wl];
            acc0 += fabsf(p0[0] - ta.x);
            acc1 += fabsf(p0[1] - ta.y);
            acc0 += fabsf(p0[2] - ta.z);
            acc1 += fabsf(p1[0] - ta.w);
            acc0 += fabsf(p1[1] - tb.x);
            acc1 += fabsf(p1[2] - tb.y);
            acc0 += fabsf(p2[0] - tb.z);
            ac1:;
            acc1 += fabsf(p2[1] - tb.w);
            acc0 += fabsf(p2[2] - t8);
        }
        __syncthreads();
    }

    bool valid = (h0 + hl) < 253 && (w0 + wl) < 253;
    g_dist0[t][tile * 256 + tid] = valid ? (acc0 + acc1) : FLT_MAX;
}

// ---------------- scale 1: ps=1, C=128, 128x128, 5 targets ----------------
__global__ __launch_bounds__(256) void scale1_kernel(
    const float* __restrict__ src, const float* __restrict__ tgt,
    const int* __restrict__ pos)
{
    __shared__ float sT[5][128];
    const int tid = threadIdx.x;
    for (int l = tid; l < 5 * 128; l += 256) {
        int t = l >> 7, c = l & 127;
        sT[t][c] = tgt[c * 16384 + pos[2 * t] * 128 + pos[2 * t + 1]];
    }
    __syncthreads();

    int p = blockIdx.x * 256 + tid;   // 0..16383
    if (p < 16129) {
        int h = p / 127, w = p - h * 127;
        const float* sp = src + h * 128 + w;
        float a0 = 0, a1 = 0, a2 = 0, a3 = 0, a4 = 0;
        #pragma unroll 4
        for (int c = 0; c < 128; ++c) {
            float s = sp[c * 16384];
            a0 += fabsf(s - sT[0][c]);
            a1 += fabsf(s - sT[1][c]);
            a2 += fabsf(s - sT[2][c]);
            a3 += fabsf(s - sT[3][c]);
            a4 += fabsf(s - sT[4][c]);
        }
        g_dist1[0][p] = a0; g_dist1[1][p] = a1; g_dist1[2][p] = a2;
        g_dist1[3][p] = a3; g_dist1[4][p] = a4;
    } else {
        g_dist1[0][p] = FLT_MAX; g_dist1[1][p] = FLT_MAX;
        g_dist1[2][p] = FLT_MAX; g_dist1[3][p] = FLT_MAX;
        g_dist1[4][p] = FLT_MAX;
    }
}

// ---------------- top-5 reduce per target ----------------
__device__ __forceinline__ void ins5(float v, float& m0, float& m1,
                                     float& m2, float& m3, float& m4)
{
    if (v < m4) {
        m4 = v;
        if (m4 < m3) { float x = m3; m3 = m4; m4 = x; }
        if (m3 < m2) { float x = m2; m2 = m3; m3 = x; }
        if (m2 < m1) { float x = m1; m1 = m2; m2 = x; }
        if (m1 < m0) { float x = m0; m0 = m1; m1 = x; }
    }
}

__global__ __launch_bounds__(256) void reduce_kernel()
{
    __shared__ float sm[256 * 5];
    const int t = blockIdx.x;     // 0..14
    const int tid = threadIdx.x;
    const float* d;
    int N;
    float inv;
    if (t < 10) { d = g_dist0[t];      N = 65536; inv = 1.0f / (576.0f * 5.0f); }
    else        { d = g_dist1[t - 10]; N = 16384; inv = 1.0f / (128.0f * 5.0f); }

    float m0 = FLT_MAX, m1 = FLT_MAX, m2 = FLT_MAX, m3 = FLT_MAX, m4 = FLT_MAX;
    for (int i = tid; i < N; i += 256)
        ins5(d[i], m0, m1, m2, m3, m4);
    sm[tid * 5 + 0] = m0; sm[tid * 5 + 1] = m1; sm[tid * 5 + 2] = m2;
    sm[tid * 5 + 3] = m3; sm[tid * 5 + 4] = m4;
    __syncthreads();

    if (tid == 0) {
        float n0 = FLT_MAX, n1 = FLT_MAX, n2 = FLT_MAX, n3 = FLT_MAX, n4 = FLT_MAX;
        for (int i = 0; i < 256 * 5; ++i)
            ins5(sm[i], n0, n1, n2, n3, n4);
        g_contrib[t] = (n0 + n1 + n2 + n3 + n4) * inv;
    }
}

__global__ void final_kernel(float* __restrict__ out)
{
    float s = 0.f;
    #pragma unroll
    for (int i = 0; i < 15; ++i) s += g_contrib[i];
    out[0] = s * 0.1f;   // / PATCH_NUM
}

// ---------------- launch ----------------
extern "C" void kernel_launch(void* const* d_in, const int* in_sizes, int n_in,
                              void* d_out, int out_size)
{
    const float* src0 = (const float*)d_in[0];
    const float* tgt0 = (const float*)d_in[1];
    const float* src1 = (const float*)d_in[2];
    const float* tgt1 = (const float*)d_in[3];
    const int*   pos0 = (const int*)d_in[4];
    const int*   pos1 = (const int*)d_in[5];

    scale0_kernel<<<dim3(256, 10), 256>>>(src0, tgt0, pos0);
    scale1_kernel<<<64, 256>>>(src1, tgt1, pos1);
    reduce_kernel<<<15, 256>>>();
    final_kernel<<<1, 1>>>((float*)d_out);
}

// round 9
// speedup vs baseline: 2.7824x; 2.7824x over previous
#include <cuda_runtime.h>
#include <float.h>

// ---------------- scratch (no allocs allowed) ----------------
__device__ float g_dist0[10][65536];   // 253*253 padded to 256*256
__device__ float g_dist1[5][16384];    // 127*127 padded
__device__ float g_contrib[16];
__device__ unsigned g_done = 0;

#define CB 16   // channel chunk for scale0

// ---------------- scale 0: ps=3, C=64, 256x256, ALL 10 targets per CTA ----
__global__ __launch_bounds__(256) void scale0_kernel(
    const float* __restrict__ src, const float* __restrict__ tgt,
    const int* __restrict__ pos)
{
    __shared__ __align__(16) float win[CB][10][34];   // (8+2) x (32+2) window
    __shared__ __align__(16) float tp4[10][64][8];    // first 8 patch elems (float4-aligned)
    __shared__ float tp1[10][64];                      // 9th patch elem

    const int tid  = threadIdx.x;
    const int tile = blockIdx.x;          // 0..255 : 8 tiles in x, 32 in y
    const int w0   = (tile & 7) * 32;
    const int h0   = (tile >> 3) * 8;
    const int hl   = tid >> 5;            // 0..7
    const int wl   = tid & 31;            // 0..31
    const int warp = tid >> 5;
    const int lane = tid & 31;

    // ---- stage ALL target patches (10 targets x 64 ch x 9) into shared ----
    #pragma unroll
    for (int k = 0; k < 9; ++k) {
        const int i = k / 3, j = k % 3;
        for (int l = tid; l < 640; l += 256) {
            int t = l >> 6, c = l & 63;
            int th = pos[2 * t], tw = pos[2 * t + 1];
            float v = tgt[c * 65536 + (th + i) * 256 + (tw + j)];
            if (k < 8) tp4[t][c][k] = v;
            else       tp1[t][c]    = v;
        }
    }

    float acc[10];
    #pragma unroll
    for (int t = 0; t < 10; ++t) acc[t] = 0.f;

    for (int cb = 0; cb < 64; cb += CB) {
        __syncthreads();
        // division-free window load: one 34-wide row per warp iteration
        for (int rr = warp; rr < CB * 10; rr += 8) {
            int c = rr & (CB - 1);
            int r = rr >> 4;                      // CB == 16
            int gy = min(h0 + r, 255);
            const float* sr = src + (cb + c) * 65536 + gy * 256;
            win[c][r][lane] = sr[min(w0 + lane, 255)];
            if (lane < 2)
                win[c][r][32 + lane] = sr[min(w0 + 32 + lane, 255)];
        }
        __syncthreads();

        #pragma unroll 2
        for (int c = 0; c < CB; ++c) {
            const int cc = cb + c;
            float s0 = win[c][hl    ][wl    ];
            float s1 = win[c][hl    ][wl + 1];
            float s2 = win[c][hl    ][wl + 2];
            float s3 = win[c][hl + 1][wl    ];
            float s4 = win[c][hl + 1][wl + 1];
            float s5 = win[c][hl + 1][wl + 2];
            float s6 = win[c][hl + 2][wl    ];
            float s7 = win[c][hl + 2][wl + 1];
            float s8 = win[c][hl + 2][wl + 2];
            #pragma unroll
            for (int t = 0; t < 10; ++t) {
                float4 a = *(const float4*)&tp4[t][cc][0];
                float4 b = *(const float4*)&tp4[t][cc][4];
                float  e = tp1[t][cc];
                float s = acc[t];
                s += fabsf(s0 - a.x);
                s += fabsf(s1 - a.y);
                s += fabsf(s2 - a.z);
                s += fabsf(s3 - a.w);
                s += fabsf(s4 - b.x);
                s += fabsf(s5 - b.y);
                s += fabsf(s6 - b.z);
                s += fabsf(s7 - b.w);
                s += fabsf(s8 - e);
                acc[t] = s;
            }
        }
    }

    const bool valid = (h0 + hl) < 253 && (w0 + wl) < 253;
    #pragma unroll
    for (int t = 0; t < 10; ++t)
        g_dist0[t][tile * 256 + tid] = valid ? acc[t] : FLT_MAX;
}

// ---------------- scale 1: ps=1, C=128, 128x128, 5 targets ----------------
__global__ __launch_bounds__(256) void scale1_kernel(
    const float* __restrict__ src, const float* __restrict__ tgt,
    const int* __restrict__ pos)
{
    __shared__ float sT[5][128];
    const int tid = threadIdx.x;
    for (int l = tid; l < 5 * 128; l += 256) {
        int t = l >> 7, c = l & 127;
        sT[t][c] = tgt[c * 16384 + pos[2 * t] * 128 + pos[2 * t + 1]];
    }
    __syncthreads();

    int p = blockIdx.x * 256 + tid;   // 0..16383
    if (p < 16129) {
        int h = p / 127, w = p - h * 127;
        const float* sp = src + h * 128 + w;
        float a0 = 0, a1 = 0, a2 = 0, a3 = 0, a4 = 0;
        #pragma unroll 4
        for (int c = 0; c < 128; ++c) {
            float s = sp[c * 16384];
            a0 += fabsf(s - sT[0][c]);
            a1 += fabsf(s - sT[1][c]);
            a2 += fabsf(s - sT[2][c]);
            a3 += fabsf(s - sT[3][c]);
            a4 += fabsf(s - sT[4][c]);
        }
        g_dist1[0][p] = a0; g_dist1[1][p] = a1; g_dist1[2][p] = a2;
        g_dist1[3][p] = a3; g_dist1[4][p] = a4;
    } else {
        g_dist1[0][p] = FLT_MAX; g_dist1[1][p] = FLT_MAX;
        g_dist1[2][p] = FLT_MAX; g_dist1[3][p] = FLT_MAX;
        g_dist1[4][p] = FLT_MAX;
    }
}

// ---------------- top-5 reduce per target (+ fused final sum) ------------
__device__ __forceinline__ void ins5(float v, float& m0, float& m1,
                                     float& m2, float& m3, float& m4)
{
    if (v < m4) {
        m4 = v;
        if (m4 < m3) { float x = m3; m3 = m4; m4 = x; }
        if (m3 < m2) { float x = m2; m2 = m3; m3 = x; }
        if (m2 < m1) { float x = m1; m1 = m2; m2 = x; }
        if (m1 < m0) { float x = m0; m0 = m1; m1 = x; }
    }
}

__global__ __launch_bounds__(256) void reduce_kernel(float* __restrict__ out)
{
    __shared__ float sm[256 * 5];
    const int t = blockIdx.x;     // 0..14
    const int tid = threadIdx.x;
    const float* d;
    int N;
    float inv;
    if (t < 10) { d = g_dist0[t];      N = 65536; inv = 1.0f / (576.0f * 5.0f); }
    else        { d = g_dist1[t - 10]; N = 16384; inv = 1.0f / (128.0f * 5.0f); }

    float m0 = FLT_MAX, m1 = FLT_MAX, m2 = FLT_MAX, m3 = FLT_MAX, m4 = FLT_MAX;
    for (int i = tid; i < N; i += 256)
        ins5(d[i], m0, m1, m2, m3, m4);
    sm[tid * 5 + 0] = m0; sm[tid * 5 + 1] = m1; sm[tid * 5 + 2] = m2;
    sm[tid * 5 + 3] = m3; sm[tid * 5 + 4] = m4;
    __syncthreads();

    // stage 2: 32 threads merge 40 values each
    if (tid < 32) {
        float n0 = FLT_MAX, n1 = FLT_MAX, n2 = FLT_MAX, n3 = FLT_MAX, n4 = FLT_MAX;
        for (int i = tid * 40; i < tid * 40 + 40; ++i)
            ins5(sm[i], n0, n1, n2, n3, n4);
        sm[tid * 5 + 0] = n0; sm[tid * 5 + 1] = n1; sm[tid * 5 + 2] = n2;
        sm[tid * 5 + 3] = n3; sm[tid * 5 + 4] = n4;
    }
    __syncthreads();

    // stage 3: thread 0 merges 160, writes contribution, last block sums
    if (tid == 0) {
        float n0 = FLT_MAX, n1 = FLT_MAX, n2 = FLT_MAX, n3 = FLT_MAX, n4 = FLT_MAX;
        for (int i = 0; i < 160; ++i)
            ins5(sm[i], n0, n1, n2, n3, n4);
        g_contrib[t] = (n0 + n1 + n2 + n3 + n4) * inv;
        __threadfence();
        unsigned v = atomicAdd(&g_done, 1u);
        if (v == 14u) {                 // deterministic: fixed-order final sum
            __threadfence();
            float s = 0.f;
            #pragma unroll
            for (int i = 0; i < 15; ++i) s += g_contrib[i];
            out[0] = s * 0.1f;          // / PATCH_NUM
            g_done = 0;                 // reset for next graph replay
        }
    }
}

// ---------------- launch ----------------
extern "C" void kernel_launch(void* const* d_in, const int* in_sizes, int n_in,
                              void* d_out, int out_size)
{
    const float* src0 = (const float*)d_in[0];
    const float* tgt0 = (const float*)d_in[1];
    const float* src1 = (const float*)d_in[2];
    const float* tgt1 = (const float*)d_in[3];
    const int*   pos0 = (const int*)d_in[4];
    const int*   pos1 = (const int*)d_in[5];

    scale0_kernel<<<256, 256>>>(src0, tgt0, pos0);
    scale1_kernel<<<64, 256>>>(src1, tgt1, pos1);
    reduce_kernel<<<15, 256>>>((float*)d_out);
}

// round 10
// speedup vs baseline: 3.2899x; 1.1824x over previous
#include <cuda_runtime.h>
#include <float.h>

// ---------------- scratch (no allocs allowed) ----------------
__device__ float g_part0[4][10][65536];   // per-channel-group partial dists, scale0
__device__ float g_part1[4][5][16384];    // scale1 partials
__device__ float g_q[15][4][5];           // per-(target,quarter) top-5
__device__ unsigned g_done = 0;

#define BIGV 1.0e30f
#define CB 8   // channel sub-chunk for scale0 window

// ---------------- scale 0: ps=3, C=64, 256x256, 10 targets --------------
// grid = (128 tiles, 4 channel-groups). Tile = 8 rows x 64 cols of patches.
// Each thread computes 2 w-adjacent patches for all 10 targets on 16 channels.
__global__ __launch_bounds__(256, 3) void scale0_kernel(
    const float* __restrict__ src, const float* __restrict__ tgt,
    const int* __restrict__ pos)
{
    __shared__ __align__(16) float win[CB][10][66];  // 10 rows x 66 cols window
    __shared__ __align__(16) float tp4[10][16][8];   // patch elems k=0..7
    __shared__ float tp1[10][16];                    // patch elem k=8

    const int tid   = threadIdx.x;
    const int tile  = blockIdx.x;           // 0..127
    const int cg    = blockIdx.y;           // 0..3  -> channels cg*16..cg*16+15
    const int w0    = (tile & 3) * 64;
    const int h0    = (tile >> 2) * 8;
    const int hl    = tid >> 5;             // 0..7 patch row
    const int lane  = tid & 31;
    const int w2    = lane * 2;             // patch cols w2, w2+1
    const int warp  = tid >> 5;
    const int cbase = cg * 16;

    // ---- stage target patches: 10 t x 16 c x 9 k ----
    #pragma unroll
    for (int k = 0; k < 9; ++k) {
        const int i = k / 3, j = k % 3;
        if (tid < 160) {
            int t = tid >> 4, c = tid & 15;
            int th = pos[2 * t], tw = pos[2 * t + 1];
            float v = tgt[(cbase + c) * 65536 + (th + i) * 256 + (tw + j)];
            if (k < 8) tp4[t][c][k] = v;
            else       tp1[t][c]    = v;
        }
    }

    float accA[10], accB[10];
    #pragma unroll
    for (int t = 0; t < 10; ++t) { accA[t] = 0.f; accB[t] = 0.f; }

    for (int cb = 0; cb < 16; cb += CB) {
        __syncthreads();
        // window load: 80 rows (8 ch x 10 rows) of 66, one row per warp-iter
        for (int rr = warp; rr < CB * 10; rr += 8) {
            int c = rr & 7;
            int r = rr >> 3;
            int gy = min(h0 + r, 255);
            const float* sr = src + (cbase + cb + c) * 65536 + gy * 256;
            win[c][r][lane]      = sr[w0 + lane];
            win[c][r][32 + lane] = sr[w0 + 32 + lane];
            if (lane < 2)
                win[c][r][64 + lane] = sr[min(w0 + 64 + lane, 255)];
        }
        __syncthreads();

        #pragma unroll 2
        for (int c = 0; c < CB; ++c) {
            const int cc = cb + c;
            // 4 cols x 3 rows of window values via LDS.64
            float2 r0a = *(const float2*)&win[c][hl    ][w2];
            float2 r0b = *(const float2*)&win[c][hl    ][w2 + 2];
            float2 r1a = *(const float2*)&win[c][hl + 1][w2];
            float2 r1b = *(const float2*)&win[c][hl + 1][w2 + 2];
            float2 r2a = *(const float2*)&win[c][hl + 2][w2];
            float2 r2b = *(const float2*)&win[c][hl + 2][w2 + 2];
            #pragma unroll
            for (int t = 0; t < 10; ++t) {
                float4 a = *(const float4*)&tp4[t][cc][0];
                float4 b = *(const float4*)&tp4[t][cc][4];
                float  e = tp1[t][cc];
                float sA = accA[t], sB = accB[t];
                sA += fabsf(r0a.x - a.x);  sB += fabsf(r0a.y - a.x);
                sA += fabsf(r0a.y - a.y);  sB += fabsf(r0b.x - a.y);
                sA += fabsf(r0b.x - a.z);  sB += fabsf(r0b.y - a.z);
                sA += fabsf(r1a.x - a.w);  sB += fabsf(r1a.y - a.w);
                sA += fabsf(r1a.y - b.x);  sB += fabsf(r1b.x - b.x);
                sA += fabsf(r1b.x - b.y);  sB += fabsf(r1b.y - b.y);
                sA += fabsf(r2a.x - b.z);  sB += fabsf(r2a.y - b.z);
                sA += fabsf(r2a.y - b.w);  sB += fabsf(r2b.x - b.w);
                sA += fabsf(r2b.x - e);    sB += fabsf(r2b.y - e);
                accA[t] = sA; accB[t] = sB;
            }
        }
    }

    const int h = h0 + hl;
    const int w = w0 + w2;
    const bool vA = (h < 253) && (w < 253);
    const bool vB = (h < 253) && (w + 1 < 253);
    const int idx = h * 256 + w;
    #pragma unroll
    for (int t = 0; t < 10; ++t) {
        float2 o;
        o.x = vA ? accA[t] : BIGV;
        o.y = vB ? accB[t] : BIGV;
        *(float2*)&g_part0[cg][t][idx] = o;
    }
}

// ---------------- scale 1: ps=1, C=128, 128x128, 5 targets ----------------
// grid = (64 p-blocks, 4 channel-groups of 32)
__global__ __launch_bounds__(256) void scale1_kernel(
    const float* __restrict__ src, const float* __restrict__ tgt,
    const int* __restrict__ pos)
{
    __shared__ float sT[5][32];
    const int tid = threadIdx.x;
    const int cg  = blockIdx.y;
    const int cbase = cg * 32;
    if (tid < 160) {
        int t = tid >> 5, c = tid & 31;
        sT[t][c] = tgt[(cbase + c) * 16384 + pos[2 * t] * 128 + pos[2 * t + 1]];
    }
    __syncthreads();

    int p = blockIdx.x * 256 + tid;   // 0..16383
    if (p < 16129) {
        int h = p / 127, w = p - h * 127;
        const float* sp = src + cbase * 16384 + h * 128 + w;
        float a0 = 0, a1 = 0, a2 = 0, a3 = 0, a4 = 0;
        #pragma unroll 4
        for (int c = 0; c < 32; ++c) {
            float s = sp[c * 16384];
            a0 += fabsf(s - sT[0][c]);
            a1 += fabsf(s - sT[1][c]);
            a2 += fabsf(s - sT[2][c]);
            a3 += fabsf(s - sT[3][c]);
            a4 += fabsf(s - sT[4][c]);
        }
        g_part1[cg][0][p] = a0; g_part1[cg][1][p] = a1; g_part1[cg][2][p] = a2;
        g_part1[cg][3][p] = a3; g_part1[cg][4][p] = a4;
    } else {
        g_part1[cg][0][p] = BIGV; g_part1[cg][1][p] = BIGV;
        g_part1[cg][2][p] = BIGV; g_part1[cg][3][p] = BIGV;
        g_part1[cg][4][p] = BIGV;
    }
}

// ---------------- top-5 reduce (partial-sum + top5 + final), 60 blocks ----
__device__ __forceinline__ void ins5(float v, float& m0, float& m1,
                                     float& m2, float& m3, float& m4)
{
    if (v < m4) {
        m4 = v;
        if (m4 < m3) { float x = m3; m3 = m4; m4 = x; }
        if (m3 < m2) { float x = m2; m2 = m3; m3 = x; }
        if (m2 < m1) { float x = m1; m1 = m2; m2 = x; }
        if (m1 < m0) { float x = m0; m0 = m1; m1 = x; }
    }
}

__global__ __launch_bounds__(512) void reduce_kernel(float* __restrict__ out)
{
    __shared__ float sm[512 * 5];
    const int b   = blockIdx.x;    // 0..59
    const int t   = b >> 2;        // 0..14
    const int q   = b & 3;         // quarter
    const int tid = threadIdx.x;

    const float *p0, *p1, *p2, *p3;
    int N;
    if (t < 10) {
        int base = q * 16384;  N = 16384;
        p0 = &g_part0[0][t][base]; p1 = &g_part0[1][t][base];
        p2 = &g_part0[2][t][base]; p3 = &g_part0[3][t][base];
    } else {
        int base = q * 4096;   N = 4096;
        p0 = &g_part1[0][t - 10][base]; p1 = &g_part1[1][t - 10][base];
        p2 = &g_part1[2][t - 10][base]; p3 = &g_part1[3][t - 10][base];
    }

    float m0 = FLT_MAX, m1 = FLT_MAX, m2 = FLT_MAX, m3 = FLT_MAX, m4 = FLT_MAX;
    for (int i = tid; i < N; i += 512) {
        float v = ((p0[i] + p1[i]) + (p2[i] + p3[i]));
        ins5(v, m0, m1, m2, m3, m4);
    }
    sm[tid * 5 + 0] = m0; sm[tid * 5 + 1] = m1; sm[tid * 5 + 2] = m2;
    sm[tid * 5 + 3] = m3; sm[tid * 5 + 4] = m4;
    __syncthreads();

    if (tid < 32) {   // 32 threads x 80 values
        float n0 = FLT_MAX, n1 = FLT_MAX, n2 = FLT_MAX, n3 = FLT_MAX, n4 = FLT_MAX;
        for (int i = tid * 80; i < tid * 80 + 80; ++i)
            ins5(sm[i], n0, n1, n2, n3, n4);
        sm[tid * 5 + 0] = n0; sm[tid * 5 + 1] = n1; sm[tid * 5 + 2] = n2;
        sm[tid * 5 + 3] = n3; sm[tid * 5 + 4] = n4;
    }
    __syncthreads();

    if (tid == 0) {
        float n0 = FLT_MAX, n1 = FLT_MAX, n2 = FLT_MAX, n3 = FLT_MAX, n4 = FLT_MAX;
        for (int i = 0; i < 160; ++i)
            ins5(sm[i], n0, n1, n2, n3, n4);
        g_q[t][q][0] = n0; g_q[t][q][1] = n1; g_q[t][q][2] = n2;
        g_q[t][q][3] = n3; g_q[t][q][4] = n4;
        __threadfence();
        unsigned v = atomicAdd(&g_done, 1u);
        if (v == 59u) {                 // last block: deterministic final merge
            __threadfence();
            float s = 0.f;
            #pragma unroll
            for (int tt = 0; tt < 15; ++tt) {
                float c0 = FLT_MAX, c1 = FLT_MAX, c2 = FLT_MAX,
                      c3 = FLT_MAX, c4 = FLT_MAX;
                #pragma unroll
                for (int qq = 0; qq < 4; ++qq)
                    #pragma unroll
                    for (int k = 0; k < 5; ++k)
                        ins5(g_q[tt][qq][k], c0, c1, c2, c3, c4);
                float inv = (tt < 10) ? (1.0f / (576.0f * 5.0f))
                                      : (1.0f / (128.0f * 5.0f));
                s += (c0 + c1 + c2 + c3 + c4) * inv;
            }
            out[0] = s * 0.1f;          // / PATCH_NUM
            g_done = 0;                 // reset for next graph replay
        }
    }
}

// ---------------- launch ----------------
extern "C" void kernel_launch(void* const* d_in, const int* in_sizes, int n_in,
                              void* d_out, int out_size)
{
    const float* src0 = (const float*)d_in[0];
    const float* tgt0 = (const float*)d_in[1];
    const float* src1 = (const float*)d_in[2];
    const float* tgt1 = (const float*)d_in[3];
    const int*   pos0 = (const int*)d_in[4];
    const int*   pos1 = (const int*)d_in[5];

    scale0_kernel<<<dim3(128, 4), 256>>>(src0, tgt0, pos0);
    scale1_kernel<<<dim3(64, 4), 256>>>(src1, tgt1, pos1);
    reduce_kernel<<<60, 512>>>((float*)d_out);
}